// round 4
// baseline (speedup 1.0000x reference)
#include <cuda_runtime.h>
#include <cstdint>
#include <cstddef>

// scratch (device globals — allocation-free rule)
__device__ float g_h[4 * 4 * 256 * 128];   // [b,h,l,x] tf32-rounded
__device__ float g_v[4 * 4 * 256 * 128];   // [b,h,k,y] tf32-rounded

__device__ __forceinline__ uint32_t f2t(float f) {
    uint32_t u;
    asm("cvt.rna.tf32.f32 %0, %1;" : "=r"(u) : "f"(f));
    return u;
}
__device__ __forceinline__ void mma8(float* c, const uint32_t* a, const uint32_t* b) {
    asm volatile(
        "mma.sync.aligned.m16n8k8.row.col.f32.tf32.tf32.f32 "
        "{%0,%1,%2,%3},{%4,%5,%6,%7},{%8,%9},{%0,%1,%2,%3};"
        : "+f"(c[0]), "+f"(c[1]), "+f"(c[2]), "+f"(c[3])
        : "r"(a[0]), "r"(a[1]), "r"(a[2]), "r"(a[3]), "r"(b[0]), "r"(b[1]));
}

// ---------------------------------------------------------------------------
// k1: fused MLP. C[m,n] = x[m,:]·Wcat[n,:], m=(b,l) in [0,1024), n in [0,1024)
// (n<512 -> Wh, else Wv). +bias, LeakyReLU(0.01), tf32-round, scatter to
// g_h/g_v[(b*4+head)*256+l][dim]. Tile 64x64, 128 threads (4 warps 2x2).
// ---------------------------------------------------------------------------
__global__ void __launch_bounds__(128) k1(
    const float* __restrict__ x,
    const float* __restrict__ Wh, const float* __restrict__ bh,
    const float* __restrict__ Wv, const float* __restrict__ bv)
{
    __shared__ uint32_t As[64][20];
    __shared__ uint32_t Bs[64][20];

    const int m0 = blockIdx.x * 64;
    const int n0g = blockIdx.y * 64;
    const bool is_h = (n0g < 512);
    const int n0 = is_h ? n0g : (n0g - 512);
    const float* Wp = is_h ? Wh : Wv;
    const float* bp = is_h ? bh : bv;
    float* outp = is_h ? g_h : g_v;

    const int t = threadIdx.x, lane = t & 31, w = t >> 5;
    const int wm = (w & 1) * 32, wn = (w >> 1) * 32;
    const int gid = lane >> 2, tig = lane & 3;
    const int lr = t >> 1, lc = (t & 1) * 8;   // load map: 8 floats/thread

    float acc[2][4][4];
#pragma unroll
    for (int i = 0; i < 2; i++)
#pragma unroll
        for (int j = 0; j < 4; j++)
#pragma unroll
            for (int r = 0; r < 4; r++) acc[i][j][r] = 0.f;

    for (int k0 = 0; k0 < 1024; k0 += 16) {
        __syncthreads();
        float4 a0 = *(const float4*)(x + (size_t)(m0 + lr) * 1024 + k0 + lc);
        float4 a1 = *(const float4*)(x + (size_t)(m0 + lr) * 1024 + k0 + lc + 4);
        float4 b0 = *(const float4*)(Wp + (size_t)(n0 + lr) * 1024 + k0 + lc);
        float4 b1 = *(const float4*)(Wp + (size_t)(n0 + lr) * 1024 + k0 + lc + 4);
        As[lr][lc] = f2t(a0.x); As[lr][lc + 1] = f2t(a0.y);
        As[lr][lc + 2] = f2t(a0.z); As[lr][lc + 3] = f2t(a0.w);
        As[lr][lc + 4] = f2t(a1.x); As[lr][lc + 5] = f2t(a1.y);
        As[lr][lc + 6] = f2t(a1.z); As[lr][lc + 7] = f2t(a1.w);
        Bs[lr][lc] = f2t(b0.x); Bs[lr][lc + 1] = f2t(b0.y);
        Bs[lr][lc + 2] = f2t(b0.z); Bs[lr][lc + 3] = f2t(b0.w);
        Bs[lr][lc + 4] = f2t(b1.x); Bs[lr][lc + 5] = f2t(b1.y);
        Bs[lr][lc + 6] = f2t(b1.z); Bs[lr][lc + 7] = f2t(b1.w);
        __syncthreads();
#pragma unroll
        for (int ks = 0; ks < 16; ks += 8) {
            uint32_t a[2][4], bf[4][2];
#pragma unroll
            for (int mt = 0; mt < 2; mt++) {
                int r = wm + mt * 16 + gid;
                a[mt][0] = As[r][ks + tig];
                a[mt][1] = As[r + 8][ks + tig];
                a[mt][2] = As[r][ks + tig + 4];
                a[mt][3] = As[r + 8][ks + tig + 4];
            }
#pragma unroll
            for (int nt = 0; nt < 4; nt++) {
                int c = wn + nt * 8 + gid;
                bf[nt][0] = Bs[c][ks + tig];
                bf[nt][1] = Bs[c][ks + tig + 4];
            }
#pragma unroll
            for (int mt = 0; mt < 2; mt++)
#pragma unroll
                for (int nt = 0; nt < 4; nt++)
                    mma8(acc[mt][nt], a[mt], bf[nt]);
        }
    }

    // epilogue
#pragma unroll
    for (int mt = 0; mt < 2; mt++)
#pragma unroll
        for (int nt = 0; nt < 4; nt++)
#pragma unroll
            for (int e = 0; e < 4; e++) {
                int m = m0 + wm + mt * 16 + gid + (e >> 1) * 8;
                int nl = wn + nt * 8 + tig * 2 + (e & 1);
                float v = acc[mt][nt][e] + bp[n0 + nl];
                v = (v > 0.f) ? v : 0.01f * v;
                int o = (n0 + nl), head = o >> 7, dim = o & 127;
                int b = m >> 8, l = m & 255;
                outp[((size_t)(b * 4 + head) * 256 + l) * 128 + dim] =
                    __uint_as_float(f2t(v));
            }
}

// ---------------------------------------------------------------------------
// k2: biaffine. Block = (d-group of 8, l-tile of 32, bh). 256 thr, 8 warps.
// Stage1: warp w computes d=dg*8+w: T[32l,128y] = h[32,128x] @ W[d][x][y]
// Stage2: out[(l,d)=256, k=256] = Ts @ v^T, K=128. Stores = full 32B sectors.
// ---------------------------------------------------------------------------
#define TSW(m) (((((m) >> 3) ^ (m)) & 7) << 2)
#define TSIDX(m, y) ((m) * 128 + ((y) ^ TSW(m)))

__global__ void __launch_bounds__(256) k2(const float* __restrict__ W,
                                          float* __restrict__ out)
{
    extern __shared__ uint32_t sm[];
    uint32_t* Ts = sm;                       // 256*128 = 32768
    uint32_t* hs = sm + 32768;               // 32*132  = 4224
    uint32_t* vs = sm + 32768 + 4224;        // 128*132 = 16896

    const int dg = blockIdx.x, lt = blockIdx.y, bhi = blockIdx.z;
    const int b = bhi >> 2, h = bhi & 3;
    const int t = threadIdx.x, lane = t & 31, w = t >> 5;
    const int gid = lane >> 2, tig = lane & 3;
    const int l0 = lt * 32;

    // load h tile [32 x 128] -> hs (stride 132)
    {
        const float* hp = g_h + ((size_t)bhi * 256 + l0) * 128;
#pragma unroll
        for (int i = 0; i < 4; i++) {
            int idx = t * 4 + i * 1024;
            int r = idx >> 7, c = idx & 127;
            float4 v4 = *(const float4*)(hp + idx);
            uint32_t* d = hs + r * 132 + c;
            d[0] = f2t(v4.x); d[1] = f2t(v4.y); d[2] = f2t(v4.z); d[3] = f2t(v4.w);
        }
    }
    __syncthreads();

    // ---- stage 1 ----
    {
        const float* Wd = W + ((size_t)(h * 128 + dg * 8 + w)) * 128 * 128; // [x][y]
#pragma unroll 1
        for (int nh = 0; nh < 2; nh++) {
            float acc[2][8][4];
#pragma unroll
            for (int i = 0; i < 2; i++)
#pragma unroll
                for (int j = 0; j < 8; j++)
#pragma unroll
                    for (int e = 0; e < 4; e++) acc[i][j][e] = 0.f;
#pragma unroll 4
            for (int ks = 0; ks < 16; ks++) {
                uint32_t a[2][4];
#pragma unroll
                for (int mt = 0; mt < 2; mt++) {
                    const uint32_t* ap = hs + (mt * 16 + gid) * 132 + ks * 8 + tig;
                    a[mt][0] = ap[0]; a[mt][1] = ap[8 * 132];
                    a[mt][2] = ap[4]; a[mt][3] = ap[8 * 132 + 4];
                }
#pragma unroll
                for (int nt = 0; nt < 8; nt++) {
                    int y = nh * 64 + nt * 8 + gid;
                    int xx = ks * 8 + tig;
                    uint32_t bf[2];
                    bf[0] = f2t(Wd[(size_t)xx * 128 + y]);
                    bf[1] = f2t(Wd[(size_t)(xx + 4) * 128 + y]);
#pragma unroll
                    for (int mt = 0; mt < 2; mt++) mma8(acc[mt][nt], a[mt], bf);
                }
            }
            // write T: m = l*8 + w
#pragma unroll
            for (int mt = 0; mt < 2; mt++)
#pragma unroll
                for (int nt = 0; nt < 8; nt++) {
                    int l = mt * 16 + gid;
                    int y = nh * 64 + nt * 8 + tig * 2;
                    Ts[TSIDX(l * 8 + w, y)]           = f2t(acc[mt][nt][0]);
                    Ts[TSIDX(l * 8 + w, y + 1)]       = f2t(acc[mt][nt][1]);
                    Ts[TSIDX((l + 8) * 8 + w, y)]     = f2t(acc[mt][nt][2]);
                    Ts[TSIDX((l + 8) * 8 + w, y + 1)] = f2t(acc[mt][nt][3]);
                }
        }
    }

    // ---- stage 2: 4 passes of N=64 (2 v-halves of 128 k) ----
    const int wm = (w & 3) * 64, wn = (w >> 2) * 32;
#pragma unroll 1
    for (int p = 0; p < 4; p++) {
        const int khalf = p >> 1, n0p = (p & 1) * 64;
        if ((p & 1) == 0) {
            __syncthreads();
            const float* vp = g_v + ((size_t)bhi * 256 + khalf * 128) * 128;
#pragma unroll
            for (int i = 0; i < 16; i++) {
                int idx = t * 4 + i * 1024;
                int r = idx >> 7, c = idx & 127;
                float4 v4 = *(const float4*)(vp + idx);
                uint32_t* d = vs + r * 132 + c;
                d[0] = f2t(v4.x); d[1] = f2t(v4.y); d[2] = f2t(v4.z); d[3] = f2t(v4.w);
            }
            __syncthreads();
        }
        float acc[4][4][4];
#pragma unroll
        for (int i = 0; i < 4; i++)
#pragma unroll
            for (int j = 0; j < 4; j++)
#pragma unroll
                for (int e = 0; e < 4; e++) acc[i][j][e] = 0.f;
#pragma unroll 4
        for (int ks = 0; ks < 16; ks++) {
            uint32_t a[4][4];
#pragma unroll
            for (int mt = 0; mt < 4; mt++) {
                int m = wm + mt * 16 + gid;
                int y = ks * 8 + tig;
                a[mt][0] = Ts[TSIDX(m, y)];
                a[mt][1] = Ts[TSIDX(m + 8, y)];
                a[mt][2] = Ts[TSIDX(m, y + 4)];
                a[mt][3] = Ts[TSIDX(m + 8, y + 4)];
            }
#pragma unroll
            for (int nt = 0; nt < 4; nt++) {
                int nn = n0p + wn + nt * 8 + gid;   // k within 128-half
                uint32_t bf[2];
                bf[0] = vs[nn * 132 + ks * 8 + tig];
                bf[1] = vs[nn * 132 + ks * 8 + tig + 4];
#pragma unroll
                for (int mt = 0; mt < 4; mt++) mma8(acc[mt][nt], a[mt], bf);
            }
        }
        // epilogue: out[b, l, k, h*128+d]
#pragma unroll
        for (int mt = 0; mt < 4; mt++)
#pragma unroll
            for (int nt = 0; nt < 4; nt++) {
                int m = wm + mt * 16 + gid;
                int k = khalf * 128 + n0p + wn + nt * 8 + tig * 2;
                int l = l0 + (m >> 3), d = dg * 8 + (m & 7);
                size_t base = (((size_t)b * 256 + l) * 256 + k) * 512 + h * 128 + d;
                out[base] = acc[mt][nt][0];
                out[base + 512] = acc[mt][nt][1];
                int m2 = m + 8;
                int l2 = l0 + (m2 >> 3);
                size_t base2 = (((size_t)b * 256 + l2) * 256 + k) * 512 + h * 128 + d;
                out[base2] = acc[mt][nt][2];
                out[base2 + 512] = acc[mt][nt][3];
            }
    }
}

extern "C" void kernel_launch(void* const* d_in, const int* in_sizes, int n_in,
                              void* d_out, int out_size)
{
    const float* x  = (const float*)d_in[0];
    const float* Wh = (const float*)d_in[1];
    const float* bh = (const float*)d_in[2];
    const float* Wv = (const float*)d_in[3];
    const float* bv = (const float*)d_in[4];
    const float* W  = (const float*)d_in[5];
    float* out = (float*)d_out;

    static bool attr_set = false;
    if (!attr_set) {
        cudaFuncSetAttribute(k2, cudaFuncAttributeMaxDynamicSharedMemorySize, 215552);
        attr_set = true;
    }

    k1<<<dim3(16, 16), 128>>>(x, Wh, bh, Wv, bv);
    k2<<<dim3(16, 8, 16), 256, 215552>>>(W, out);
}